// round 7
// baseline (speedup 1.0000x reference)
#include <cuda_runtime.h>
#include <cstdint>
#include <cstddef>

#define NB 32
#define DD 128
#define NN 4096
#define NC 64
#define DR 25

// output layout: logits | cam | bag | x
#define OUT_CAM  ((size_t)2048)
#define OUT_BAG  ((size_t)8390656)   // 2048 + 32*64*4096
#define OUT_X    ((size_t)8394752)   // + 32*128

__device__ float g_peT[DD * NN];     // 2 MB transposed pe
__device__ float g_bag[NB * DD];

static __device__ __forceinline__ unsigned long long ffma2(unsigned long long a,
                                                           unsigned long long b,
                                                           unsigned long long c) {
    unsigned long long d;
    asm("fma.rn.f32x2 %0, %1, %2, %3;" : "=l"(d) : "l"(a), "l"(b), "l"(c));
    return d;
}
static __device__ __forceinline__ unsigned long long dup2(float f) {
    unsigned long long d;
    asm("mov.b64 %0, {%1, %1};" : "=l"(d) : "f"(f));
    return d;
}
static __device__ __forceinline__ unsigned long long pack2(float a, float b) {
    unsigned long long d;
    asm("mov.b64 %0, {%1, %2};" : "=l"(d) : "f"(a), "f"(b));
    return d;
}
static __device__ __forceinline__ float2 unpack2(unsigned long long v) {
    float2 r;
    asm("mov.b64 {%0, %1}, %2;" : "=f"(r.x), "=f"(r.y) : "l"(v));
    return r;
}

// ---------------- pe transpose: g_peT[d][n] = pe[n][d] ----------------
__global__ void k_transpose(const float* __restrict__ pe) {
    __shared__ float t[32][33];
    int n0 = blockIdx.x * 32, d0 = blockIdx.y * 32;
    int tx = threadIdx.x, ty = threadIdx.y;  // 32 x 8
#pragma unroll
    for (int j = 0; j < 32; j += 8)
        t[ty + j][tx] = pe[(size_t)(n0 + ty + j) * DD + d0 + tx];
    __syncthreads();
#pragma unroll
    for (int j = 0; j < 32; j += 8)
        g_peT[(size_t)(d0 + ty + j) * NN + n0 + tx] = t[tx][ty + j];
}

// epilogue: rank mask (stable ties) + cam store for one column
#define EPILOG(ACC, NCOL)                                                      \
    do {                                                                       \
        float s[NC];                                                           \
        _Pragma("unroll") for (int cp = 0; cp < 32; ++cp) {                    \
            float2 v = unpack2(ACC[cp]);                                       \
            s[2 * cp] = v.x;                                                   \
            s[2 * cp + 1] = v.y;                                               \
        }                                                                      \
        unsigned kLo = 0u, kHi = 0u;                                           \
        _Pragma("unroll") for (int i = 0; i < DR; ++i) {                       \
            int r = 0;                                                         \
            _Pragma("unroll") for (int j = 0; j < NC; ++j)                     \
                r += (s[j] > s[i]) ? 1 : 0;                                    \
            _Pragma("unroll") for (int j = 0; j < i; ++j)                      \
                r += (s[j] == s[i]) ? 1 : 0;                                   \
            if (r < 32) kLo |= (1u << r);                                      \
            else        kHi |= (1u << (r - 32));                               \
        }                                                                      \
        _Pragma("unroll") for (int r = 0; r < NC; ++r) {                       \
            unsigned bit = (r < 32) ? ((kLo >> r) & 1u) : ((kHi >> (r - 32)) & 1u); \
            camOut[(size_t)r * NN + (NCOL)] = bit ? s[r] : 0.0f;               \
        }                                                                      \
    } while (0)

// ---------------- main: e = fl(x+pe) joint, strictly sequential fp32 FMA over
//                  d=0..127 per class (Eigen gebp order), 2 columns/thread ----
__global__ void __launch_bounds__(128, 2) k_main(const float* __restrict__ x,
                                                 const float* __restrict__ W,
                                                 float* __restrict__ out) {
    // W2s[d][cp] = ( W[2cp][d], W[2cp+1][d] ),  d in 0..127, cp in 0..31. 32KB.
    __shared__ __align__(16) unsigned long long W2s[DD * 32];
    int tid = threadIdx.x;
    int b = blockIdx.y;
    int nA = blockIdx.x * 256 + tid;
    int nB = nA + 128;

    for (int idx = tid; idx < DD * 32; idx += 128) {
        int d = idx >> 5, cp = idx & 31;
        W2s[idx] = pack2(W[(2 * cp) * DD + d], W[(2 * cp + 1) * DD + d]);
    }
    __syncthreads();

    const float* xb = x + (size_t)b * DD * NN;
    float* xcopy = out + OUT_X + (size_t)b * DD * NN;

    unsigned long long accA[32], accB[32];
#pragma unroll
    for (int cp = 0; cp < 32; ++cp) { accA[cp] = 0ull; accB[cp] = 0ull; }

#pragma unroll 2
    for (int d = 0; d < DD; ++d) {
        float xa = xb[(size_t)d * NN + nA];
        float xv = xb[(size_t)d * NN + nB];
        xcopy[(size_t)d * NN + nA] = xa;
        xcopy[(size_t)d * NN + nB] = xv;
        float eA = xa + g_peT[(size_t)d * NN + nA];   // fl(x+pe), matches ref
        float eB = xv + g_peT[(size_t)d * NN + nB];
        unsigned long long e2A = dup2(eA), e2B = dup2(eB);
        const ulonglong2* wrow = (const ulonglong2*)&W2s[d * 32];  // uniform -> broadcast
#pragma unroll
        for (int q = 0; q < 16; ++q) {
            ulonglong2 w = wrow[q];
            accA[2 * q]     = ffma2(w.x, e2A, accA[2 * q]);
            accB[2 * q]     = ffma2(w.x, e2B, accB[2 * q]);
            accA[2 * q + 1] = ffma2(w.y, e2A, accA[2 * q + 1]);
            accB[2 * q + 1] = ffma2(w.y, e2B, accB[2 * q + 1]);
        }
    }

    float* camOut = out + OUT_CAM + (size_t)b * NC * NN;
    EPILOG(accA, nA);
    EPILOG(accB, nB);
}

// ---------------- bag: exact top-25 mean per (b,d) row ----------------
// Per-warp hi16 binary search (vset2, no barriers) -> T0 = max over warps ->
// gather candidates (hi16 >= T0, superset of top-25) -> warp0 exact 32-bit
// search -> exact tie-filled mean.
__global__ void __launch_bounds__(256) k_bag(const float* __restrict__ x,
                                             float* __restrict__ out) {
    __shared__ unsigned cand[NN];
    __shared__ unsigned s_T0;
    __shared__ int s_nc;
    __shared__ unsigned s_K;
    __shared__ float wsum[8];
    __shared__ int wcnt[8];

    int row = blockIdx.x;            // row = b*128 + d
    int d = row & 127;
    int tid = threadIdx.x;
    int lane = tid & 31, wid = tid >> 5;
    const float* xr = x + (size_t)row * NN;
    const float* pr = g_peT + (size_t)d * NN;

    if (tid == 0) { s_T0 = 0u; s_nc = 0; }

    unsigned key[16];
#pragma unroll
    for (int k = 0; k < 16; ++k) {
        int n = tid + (k << 8);
        float e = xr[n] + pr[n];
        unsigned u = __float_as_uint(e);
        key[k] = (u & 0x80000000u) ? ~u : (u | 0x80000000u);
    }

    // packed hi16 pairs: h[j] = hi16(key[2j]) in low half, hi16(key[2j+1]) in high half
    unsigned h[8];
#pragma unroll
    for (int j = 0; j < 8; ++j)
        h[j] = (key[2 * j] >> 16) | (key[2 * j + 1] & 0xFFFF0000u);

    // per-warp binary search: 25th largest hi16 among this warp's 512 elements
    unsigned Kw = 0u;
#pragma unroll
    for (int bit = 15; bit >= 0; --bit) {
        unsigned test = Kw | (1u << bit);
        unsigned tp = test | (test << 16);
        unsigned c2 = 0u;
#pragma unroll
        for (int j = 0; j < 8; ++j) c2 += __vsetgeu2(h[j], tp);
        int c = (int)((c2 & 0xFFFFu) + (c2 >> 16));
        c = __reduce_add_sync(0xFFFFFFFFu, c);
        if (c >= DR) Kw = test;
    }

    __syncthreads();                 // s_T0/s_nc init visible
    if (lane == 0) atomicMax(&s_T0, Kw);
    __syncthreads();
    unsigned T0 = s_T0;

    // gather candidates: hi16 >= T0  (provably contains all top-25 keys)
#pragma unroll
    for (int k = 0; k < 16; ++k) {
        if ((key[k] >> 16) >= T0) {
            int p = atomicAdd(&s_nc, 1);
            cand[p] = key[k];
        }
    }
    __syncthreads();

    // warp0: exact 32-bit binary search for 25th largest among candidates
    if (wid == 0) {
        int m = s_nc;
        unsigned K = 0u;
        for (int bit = 31; bit >= 0; --bit) {
            unsigned test = K | (1u << bit);
            int c = 0;
            for (int i = lane; i < m; i += 32)
                c += (cand[i] >= test) ? 1 : 0;
            c = __reduce_add_sync(0xFFFFFFFFu, c);
            if (c >= DR) K = test;
        }
        if (lane == 0) s_K = K;
    }
    __syncthreads();
    unsigned K = s_K;

    // exact mean of top-25 with tie fill at K
    int cg = 0;
    float sm = 0.f;
#pragma unroll
    for (int k = 0; k < 16; ++k) {
        if (key[k] > K) {
            cg++;
            unsigned u = (key[k] & 0x80000000u) ? (key[k] ^ 0x80000000u) : ~key[k];
            sm += __uint_as_float(u);
        }
    }
#pragma unroll
    for (int off = 16; off > 0; off >>= 1) {
        cg += __shfl_down_sync(0xFFFFFFFFu, cg, off);
        sm += __shfl_down_sync(0xFFFFFFFFu, sm, off);
    }
    if (lane == 0) { wcnt[wid] = cg; wsum[wid] = sm; }
    __syncthreads();
    if (tid == 0) {
        int cgt = wcnt[0] + wcnt[1] + wcnt[2] + wcnt[3] + wcnt[4] + wcnt[5] + wcnt[6] + wcnt[7];
        float smt = wsum[0] + wsum[1] + wsum[2] + wsum[3] + wsum[4] + wsum[5] + wsum[6] + wsum[7];
        unsigned kk = (K & 0x80000000u) ? (K ^ 0x80000000u) : ~K;
        float kv = __uint_as_float(kk);
        float bag = (smt + (float)(DR - cgt) * kv) * (1.0f / 25.0f);
        g_bag[row] = bag;
        out[OUT_BAG + row] = bag;
    }
}

// ---------------- logits = bag @ W^T + b ----------------
__global__ void __launch_bounds__(64) k_logits(const float* __restrict__ W,
                                               const float* __restrict__ bias,
                                               float* __restrict__ out) {
    int b = blockIdx.x, c = threadIdx.x;
    const float4* bg = (const float4*)(g_bag + b * DD);
    const float4* w4 = (const float4*)(W + c * DD);
    float a = 0.f;
#pragma unroll
    for (int q = 0; q < 32; ++q) {
        float4 g = bg[q];
        float4 w = __ldg(&w4[q]);
        a += g.x * w.x + g.y * w.y + g.z * w.z + g.w * w.w;
    }
    out[(size_t)b * NC + c] = a + bias[c];
}

extern "C" void kernel_launch(void* const* d_in, const int* in_sizes, int n_in,
                              void* d_out, int out_size) {
    const float* x    = (const float*)d_in[0];
    const float* W    = (const float*)d_in[1];
    const float* bias = (const float*)d_in[2];
    const float* pe   = (const float*)d_in[3];
    float* out = (float*)d_out;

    k_transpose<<<dim3(128, 4), dim3(32, 8)>>>(pe);
    k_main<<<dim3(16, 32), 128>>>(x, W, out);
    k_bag<<<4096, 256>>>(x, out);
    k_logits<<<32, 64>>>(W, bias, out);
}

// round 9
// speedup vs baseline: 1.3521x; 1.3521x over previous
#include <cuda_runtime.h>
#include <cstdint>
#include <cstddef>

#define NB 32
#define DD 128
#define NN 4096
#define NC 64
#define DR 25

// output layout: logits | cam | bag | x
#define OUT_CAM  ((size_t)2048)
#define OUT_BAG  ((size_t)8390656)   // 2048 + 32*64*4096
#define OUT_X    ((size_t)8394752)   // + 32*128

__device__ float g_peT[DD * NN];     // 2 MB transposed pe
__device__ float g_bag[NB * DD];

static __device__ __forceinline__ unsigned long long ffma2(unsigned long long a,
                                                           unsigned long long b,
                                                           unsigned long long c) {
    unsigned long long d;
    asm("fma.rn.f32x2 %0, %1, %2, %3;" : "=l"(d) : "l"(a), "l"(b), "l"(c));
    return d;
}
static __device__ __forceinline__ unsigned long long dup2(float f) {
    unsigned long long d;
    asm("mov.b64 %0, {%1, %1};" : "=l"(d) : "f"(f));
    return d;
}
static __device__ __forceinline__ unsigned long long pack2(float a, float b) {
    unsigned long long d;
    asm("mov.b64 %0, {%1, %2};" : "=l"(d) : "f"(a), "f"(b));
    return d;
}
static __device__ __forceinline__ float2 unpack2(unsigned long long v) {
    float2 r;
    asm("mov.b64 {%0, %1}, %2;" : "=f"(r.x), "=f"(r.y) : "l"(v));
    return r;
}

// ---------------- pe transpose: g_peT[d][n] = pe[n][d] ----------------
__global__ void k_transpose(const float* __restrict__ pe) {
    __shared__ float t[32][33];
    int n0 = blockIdx.x * 32, d0 = blockIdx.y * 32;
    int tx = threadIdx.x, ty = threadIdx.y;  // 32 x 8
#pragma unroll
    for (int j = 0; j < 32; j += 8)
        t[ty + j][tx] = pe[(size_t)(n0 + ty + j) * DD + d0 + tx];
    __syncthreads();
#pragma unroll
    for (int j = 0; j < 32; j += 8)
        g_peT[(size_t)(d0 + ty + j) * NN + n0 + tx] = t[tx][ty + j];
}

// ---------------- main: e = fl(x+pe) joint, then STRICTLY SEQUENTIAL fp32 FMA
//                  over d=0..127 per class (Eigen gebp order). Class-paired
//                  f32x2: each lane is one class's full sequential chain. ----
__global__ void __launch_bounds__(128) k_main(const float* __restrict__ x,
                                              const float* __restrict__ W,
                                              float* __restrict__ out) {
    // W2s[d][cp] = ( W[2cp][d], W[2cp+1][d] ),  d in 0..127, cp in 0..31. 32KB.
    __shared__ __align__(16) unsigned long long W2s[DD * 32];
    int tid = threadIdx.x;
    int b = blockIdx.y;
    int n = blockIdx.x * 128 + tid;

    for (int idx = tid; idx < DD * 32; idx += 128) {
        int d = idx >> 5, cp = idx & 31;
        W2s[idx] = pack2(W[(2 * cp) * DD + d], W[(2 * cp + 1) * DD + d]);
    }
    __syncthreads();

    const float* xb = x + (size_t)b * DD * NN;
    float* xcopy = out + OUT_X + (size_t)b * DD * NN;

    unsigned long long acc[32];
#pragma unroll
    for (int cp = 0; cp < 32; ++cp) acc[cp] = 0ull;

#pragma unroll 4
    for (int d = 0; d < DD; ++d) {
        float xa = xb[(size_t)d * NN + n];
        xcopy[(size_t)d * NN + n] = xa;
        float e = xa + g_peT[(size_t)d * NN + n];   // fl(x+pe), matches ref
        unsigned long long e2 = dup2(e);
        const ulonglong2* wrow = (const ulonglong2*)&W2s[d * 32];  // warp-uniform -> broadcast
#pragma unroll
        for (int q = 0; q < 16; ++q) {
            ulonglong2 w = wrow[q];
            acc[2 * q]     = ffma2(w.x, e2, acc[2 * q]);
            acc[2 * q + 1] = ffma2(w.y, e2, acc[2 * q + 1]);
        }
    }

    float s[NC];
#pragma unroll
    for (int cp = 0; cp < 32; ++cp) {
        float2 v = unpack2(acc[cp]);
        s[2 * cp] = v.x;
        s[2 * cp + 1] = v.y;
    }

    // rank mask: keep slot r iff the class ranked r-th (stable) has index < DR
    unsigned kLo = 0u, kHi = 0u;
#pragma unroll
    for (int i = 0; i < DR; ++i) {
        int r = 0;
#pragma unroll
        for (int j = 0; j < NC; ++j) r += (s[j] > s[i]) ? 1 : 0;
#pragma unroll
        for (int j = 0; j < i; ++j)               // stable-tie correction
            r += (s[j] == s[i]) ? 1 : 0;
        if (r < 32) kLo |= (1u << r);
        else        kHi |= (1u << (r - 32));
    }

    float* camOut = out + OUT_CAM + (size_t)b * NC * NN;
#pragma unroll
    for (int r = 0; r < NC; ++r) {
        unsigned bit = (r < 32) ? ((kLo >> r) & 1u) : ((kHi >> (r - 32)) & 1u);
        camOut[(size_t)r * NN + n] = bit ? s[r] : 0.0f;
    }
}

// ---------------- bag: exact top-25 mean per (b,d) row ----------------
// Per-warp hi16 binary search (vset2, no barriers) -> T0 = max over warps ->
// gather candidates (hi16 >= T0, superset of top-25) -> warp0 exact 32-bit
// search -> exact tie-filled mean.
__global__ void __launch_bounds__(256) k_bag(const float* __restrict__ x,
                                             float* __restrict__ out) {
    __shared__ unsigned cand[NN];
    __shared__ unsigned s_T0;
    __shared__ int s_nc;
    __shared__ unsigned s_K;
    __shared__ float wsum[8];
    __shared__ int wcnt[8];

    int row = blockIdx.x;            // row = b*128 + d
    int d = row & 127;
    int tid = threadIdx.x;
    int lane = tid & 31, wid = tid >> 5;
    const float* xr = x + (size_t)row * NN;
    const float* pr = g_peT + (size_t)d * NN;

    if (tid == 0) { s_T0 = 0u; s_nc = 0; }

    unsigned key[16];
#pragma unroll
    for (int k = 0; k < 16; ++k) {
        int n = tid + (k << 8);
        float e = xr[n] + pr[n];
        unsigned u = __float_as_uint(e);
        key[k] = (u & 0x80000000u) ? ~u : (u | 0x80000000u);
    }

    // packed hi16 pairs: h[j] = hi16(key[2j]) in low half, hi16(key[2j+1]) in high half
    unsigned h[8];
#pragma unroll
    for (int j = 0; j < 8; ++j)
        h[j] = (key[2 * j] >> 16) | (key[2 * j + 1] & 0xFFFF0000u);

    // per-warp binary search: 25th largest hi16 among this warp's 512 elements
    unsigned Kw = 0u;
#pragma unroll
    for (int bit = 15; bit >= 0; --bit) {
        unsigned test = Kw | (1u << bit);
        unsigned tp = test | (test << 16);
        unsigned c2 = 0u;
#pragma unroll
        for (int j = 0; j < 8; ++j) c2 += __vsetgeu2(h[j], tp);
        int c = (int)((c2 & 0xFFFFu) + (c2 >> 16));
        c = __reduce_add_sync(0xFFFFFFFFu, c);
        if (c >= DR) Kw = test;
    }

    __syncthreads();                 // s_T0/s_nc init visible
    if (lane == 0) atomicMax(&s_T0, Kw);
    __syncthreads();
    unsigned T0 = s_T0;

    // gather candidates: hi16 >= T0  (provably contains all top-25 keys)
#pragma unroll
    for (int k = 0; k < 16; ++k) {
        if ((key[k] >> 16) >= T0) {
            int p = atomicAdd(&s_nc, 1);
            cand[p] = key[k];
        }
    }
    __syncthreads();

    // warp0: exact 32-bit binary search for 25th largest among candidates
    if (wid == 0) {
        int m = s_nc;
        unsigned K = 0u;
        for (int bit = 31; bit >= 0; --bit) {
            unsigned test = K | (1u << bit);
            int c = 0;
            for (int i = lane; i < m; i += 32)
                c += (cand[i] >= test) ? 1 : 0;
            c = __reduce_add_sync(0xFFFFFFFFu, c);
            if (c >= DR) K = test;
        }
        if (lane == 0) s_K = K;
    }
    __syncthreads();
    unsigned K = s_K;

    // exact mean of top-25 with tie fill at K
    int cg = 0;
    float sm = 0.f;
#pragma unroll
    for (int k = 0; k < 16; ++k) {
        if (key[k] > K) {
            cg++;
            unsigned u = (key[k] & 0x80000000u) ? (key[k] ^ 0x80000000u) : ~key[k];
            sm += __uint_as_float(u);
        }
    }
#pragma unroll
    for (int off = 16; off > 0; off >>= 1) {
        cg += __shfl_down_sync(0xFFFFFFFFu, cg, off);
        sm += __shfl_down_sync(0xFFFFFFFFu, sm, off);
    }
    if (lane == 0) { wcnt[wid] = cg; wsum[wid] = sm; }
    __syncthreads();
    if (tid == 0) {
        int cgt = wcnt[0] + wcnt[1] + wcnt[2] + wcnt[3] + wcnt[4] + wcnt[5] + wcnt[6] + wcnt[7];
        float smt = wsum[0] + wsum[1] + wsum[2] + wsum[3] + wsum[4] + wsum[5] + wsum[6] + wsum[7];
        unsigned kk = (K & 0x80000000u) ? (K ^ 0x80000000u) : ~K;
        float kv = __uint_as_float(kk);
        float bag = (smt + (float)(DR - cgt) * kv) * (1.0f / 25.0f);
        g_bag[row] = bag;
        out[OUT_BAG + row] = bag;
    }
}

// ---------------- logits = bag @ W^T + b ----------------
__global__ void __launch_bounds__(64) k_logits(const float* __restrict__ W,
                                               const float* __restrict__ bias,
                                               float* __restrict__ out) {
    int b = blockIdx.x, c = threadIdx.x;
    const float4* bg = (const float4*)(g_bag + b * DD);
    const float4* w4 = (const float4*)(W + c * DD);
    float a = 0.f;
#pragma unroll
    for (int q = 0; q < 32; ++q) {
        float4 g = bg[q];
        float4 w = __ldg(&w4[q]);
        a += g.x * w.x + g.y * w.y + g.z * w.z + g.w * w.w;
    }
    out[(size_t)b * NC + c] = a + bias[c];
}

extern "C" void kernel_launch(void* const* d_in, const int* in_sizes, int n_in,
                              void* d_out, int out_size) {
    const float* x    = (const float*)d_in[0];
    const float* W    = (const float*)d_in[1];
    const float* bias = (const float*)d_in[2];
    const float* pe   = (const float*)d_in[3];
    float* out = (float*)d_out;

    k_transpose<<<dim3(128, 4), dim3(32, 8)>>>(pe);
    k_main<<<dim3(32, 32), 128>>>(x, W, out);
    k_bag<<<4096, 256>>>(x, out);
    k_logits<<<32, 64>>>(W, bias, out);
}

// round 10
// speedup vs baseline: 1.3742x; 1.0163x over previous
#include <cuda_runtime.h>
#include <cstdint>
#include <cstddef>

#define NB 32
#define DD 128
#define NN 4096
#define NC 64
#define DR 25

// output layout: logits | cam | bag | x
#define OUT_CAM  ((size_t)2048)
#define OUT_BAG  ((size_t)8390656)   // 2048 + 32*64*4096
#define OUT_X    ((size_t)8394752)   // + 32*128

__device__ float g_peT[DD * NN];     // 2 MB transposed pe
__device__ float g_bag[NB * DD];

static __device__ __forceinline__ unsigned long long ffma2(unsigned long long a,
                                                           unsigned long long b,
                                                           unsigned long long c) {
    unsigned long long d;
    asm("fma.rn.f32x2 %0, %1, %2, %3;" : "=l"(d) : "l"(a), "l"(b), "l"(c));
    return d;
}
static __device__ __forceinline__ unsigned long long dup2(float f) {
    unsigned long long d;
    asm("mov.b64 %0, {%1, %1};" : "=l"(d) : "f"(f));
    return d;
}
static __device__ __forceinline__ unsigned long long pack2(float a, float b) {
    unsigned long long d;
    asm("mov.b64 %0, {%1, %2};" : "=l"(d) : "f"(a), "f"(b));
    return d;
}
static __device__ __forceinline__ float2 unpack2(unsigned long long v) {
    float2 r;
    asm("mov.b64 {%0, %1}, %2;" : "=f"(r.x), "=f"(r.y) : "l"(v));
    return r;
}

// ---------------- pe transpose: g_peT[d][n] = pe[n][d] ----------------
__global__ void k_transpose(const float* __restrict__ pe) {
    __shared__ float t[32][33];
    int n0 = blockIdx.x * 32, d0 = blockIdx.y * 32;
    int tx = threadIdx.x, ty = threadIdx.y;  // 32 x 8
#pragma unroll
    for (int j = 0; j < 32; j += 8)
        t[ty + j][tx] = pe[(size_t)(n0 + ty + j) * DD + d0 + tx];
    __syncthreads();
#pragma unroll
    for (int j = 0; j < 32; j += 8)
        g_peT[(size_t)(d0 + ty + j) * NN + n0 + tx] = t[tx][ty + j];
}

// ---------------- main: e = fl(x+pe) joint, then STRICTLY SEQUENTIAL fp32 FMA
//                  over d=0..127 per class (Eigen gebp order). Class-paired
//                  f32x2: each lane is one class's full sequential chain. ----
__global__ void __launch_bounds__(128) k_main(const float* __restrict__ x,
                                              const float* __restrict__ W,
                                              float* __restrict__ out) {
    // W2s[d][cp] = ( W[2cp][d], W[2cp+1][d] ),  d in 0..127, cp in 0..31. 32KB.
    __shared__ __align__(16) unsigned long long W2s[DD * 32];
    int tid = threadIdx.x;
    int b = blockIdx.y;
    int n = blockIdx.x * 128 + tid;

    for (int idx = tid; idx < DD * 32; idx += 128) {
        int d = idx >> 5, cp = idx & 31;
        W2s[idx] = pack2(W[(2 * cp) * DD + d], W[(2 * cp + 1) * DD + d]);
    }
    __syncthreads();

    const float* xb = x + (size_t)b * DD * NN;
    float* xcopy = out + OUT_X + (size_t)b * DD * NN;

    unsigned long long acc[32];
#pragma unroll
    for (int cp = 0; cp < 32; ++cp) acc[cp] = 0ull;

#pragma unroll 4
    for (int d = 0; d < DD; ++d) {
        float xa = xb[(size_t)d * NN + n];
        xcopy[(size_t)d * NN + n] = xa;
        float e = xa + g_peT[(size_t)d * NN + n];   // fl(x+pe), matches ref
        unsigned long long e2 = dup2(e);
        const ulonglong2* wrow = (const ulonglong2*)&W2s[d * 32];  // warp-uniform -> broadcast
#pragma unroll
        for (int q = 0; q < 16; ++q) {
            ulonglong2 w = wrow[q];
            acc[2 * q]     = ffma2(w.x, e2, acc[2 * q]);
            acc[2 * q + 1] = ffma2(w.y, e2, acc[2 * q + 1]);
        }
    }

    float s[NC];
#pragma unroll
    for (int cp = 0; cp < 32; ++cp) {
        float2 v = unpack2(acc[cp]);
        s[2 * cp] = v.x;
        s[2 * cp + 1] = v.y;
    }

    // rank mask: keep slot r iff the class ranked r-th (stable) has index < DR
    unsigned kLo = 0u, kHi = 0u;
#pragma unroll
    for (int i = 0; i < DR; ++i) {
        int r = 0;
#pragma unroll
        for (int j = 0; j < NC; ++j) r += (s[j] > s[i]) ? 1 : 0;
#pragma unroll
        for (int j = 0; j < i; ++j)               // stable-tie correction
            r += (s[j] == s[i]) ? 1 : 0;
        if (r < 32) kLo |= (1u << r);
        else        kHi |= (1u << (r - 32));
    }

    float* camOut = out + OUT_CAM + (size_t)b * NC * NN;
#pragma unroll
    for (int r = 0; r < NC; ++r) {
        unsigned bit = (r < 32) ? ((kLo >> r) & 1u) : ((kHi >> (r - 32)) & 1u);
        camOut[(size_t)r * NN + n] = bit ? s[r] : 0.0f;
    }
}

// ---------------- bag: exact top-25 mean per (b,d) row ----------------
// Per-warp hi16 binary search (vset2, no barriers) -> T0 = max over warps ->
// gather candidates (hi16 >= T0, superset of top-25) -> warp0 exact 32-bit
// search -> exact tie-filled mean.
__global__ void __launch_bounds__(256) k_bag(const float* __restrict__ x,
                                             float* __restrict__ out) {
    __shared__ unsigned cand[NN];
    __shared__ unsigned s_T0;
    __shared__ int s_nc;
    __shared__ unsigned s_K;
    __shared__ float wsum[8];
    __shared__ int wcnt[8];

    int row = blockIdx.x;            // row = b*128 + d
    int d = row & 127;
    int tid = threadIdx.x;
    int lane = tid & 31, wid = tid >> 5;
    const float* xr = x + (size_t)row * NN;
    const float* pr = g_peT + (size_t)d * NN;

    if (tid == 0) { s_T0 = 0u; s_nc = 0; }

    unsigned key[16];
#pragma unroll
    for (int k = 0; k < 16; ++k) {
        int n = tid + (k << 8);
        float e = xr[n] + pr[n];
        unsigned u = __float_as_uint(e);
        key[k] = (u & 0x80000000u) ? ~u : (u | 0x80000000u);
    }

    // packed hi16 pairs: h[j] = hi16(key[2j]) in low half, hi16(key[2j+1]) in high half
    unsigned h[8];
#pragma unroll
    for (int j = 0; j < 8; ++j)
        h[j] = (key[2 * j] >> 16) | (key[2 * j + 1] & 0xFFFF0000u);

    // per-warp binary search: 25th largest hi16 among this warp's 512 elements
    unsigned Kw = 0u;
#pragma unroll
    for (int bit = 15; bit >= 0; --bit) {
        unsigned test = Kw | (1u << bit);
        unsigned tp = test | (test << 16);
        unsigned c2 = 0u;
#pragma unroll
        for (int j = 0; j < 8; ++j) c2 += __vsetgeu2(h[j], tp);
        int c = (int)((c2 & 0xFFFFu) + (c2 >> 16));
        c = __reduce_add_sync(0xFFFFFFFFu, c);
        if (c >= DR) Kw = test;
    }

    __syncthreads();                 // s_T0/s_nc init visible
    if (lane == 0) atomicMax(&s_T0, Kw);
    __syncthreads();
    unsigned T0 = s_T0;

    // gather candidates: hi16 >= T0  (provably contains all top-25 keys)
#pragma unroll
    for (int k = 0; k < 16; ++k) {
        if ((key[k] >> 16) >= T0) {
            int p = atomicAdd(&s_nc, 1);
            cand[p] = key[k];
        }
    }
    __syncthreads();

    // warp0: exact 32-bit binary search for 25th largest among candidates
    if (wid == 0) {
        int m = s_nc;
        unsigned K = 0u;
        for (int bit = 31; bit >= 0; --bit) {
            unsigned test = K | (1u << bit);
            int c = 0;
            for (int i = lane; i < m; i += 32)
                c += (cand[i] >= test) ? 1 : 0;
            c = __reduce_add_sync(0xFFFFFFFFu, c);
            if (c >= DR) K = test;
        }
        if (lane == 0) s_K = K;
    }
    __syncthreads();
    unsigned K = s_K;

    // exact mean of top-25 with tie fill at K
    int cg = 0;
    float sm = 0.f;
#pragma unroll
    for (int k = 0; k < 16; ++k) {
        if (key[k] > K) {
            cg++;
            unsigned u = (key[k] & 0x80000000u) ? (key[k] ^ 0x80000000u) : ~key[k];
            sm += __uint_as_float(u);
        }
    }
#pragma unroll
    for (int off = 16; off > 0; off >>= 1) {
        cg += __shfl_down_sync(0xFFFFFFFFu, cg, off);
        sm += __shfl_down_sync(0xFFFFFFFFu, sm, off);
    }
    if (lane == 0) { wcnt[wid] = cg; wsum[wid] = sm; }
    __syncthreads();
    if (tid == 0) {
        int cgt = wcnt[0] + wcnt[1] + wcnt[2] + wcnt[3] + wcnt[4] + wcnt[5] + wcnt[6] + wcnt[7];
        float smt = wsum[0] + wsum[1] + wsum[2] + wsum[3] + wsum[4] + wsum[5] + wsum[6] + wsum[7];
        unsigned kk = (K & 0x80000000u) ? (K ^ 0x80000000u) : ~K;
        float kv = __uint_as_float(kk);
        float bag = (smt + (float)(DR - cgt) * kv) * (1.0f / 25.0f);
        g_bag[row] = bag;
        out[OUT_BAG + row] = bag;
    }
}

// ---------------- logits = bag @ W^T + b  (warp per 8 c's, float4 + shfl) ----
__global__ void __launch_bounds__(256) k_logits(const float* __restrict__ W,
                                                const float* __restrict__ bias,
                                                float* __restrict__ out) {
    int b = blockIdx.x;
    int lane = threadIdx.x & 31, wid = threadIdx.x >> 5;   // 8 warps
    float4 g = ((const float4*)(g_bag + b * DD))[lane];    // lane covers d=4l..4l+3
#pragma unroll
    for (int i = 0; i < 8; ++i) {
        int c = wid * 8 + i;
        float4 w = __ldg((const float4*)(W + c * DD) + lane);
        float p = g.x * w.x + g.y * w.y + g.z * w.z + g.w * w.w;
#pragma unroll
        for (int off = 16; off > 0; off >>= 1)
            p += __shfl_down_sync(0xFFFFFFFFu, p, off);
        if (lane == 0) out[(size_t)b * NC + c] = p + bias[c];
    }
}

extern "C" void kernel_launch(void* const* d_in, const int* in_sizes, int n_in,
                              void* d_out, int out_size) {
    const float* x    = (const float*)d_in[0];
    const float* W    = (const float*)d_in[1];
    const float* bias = (const float*)d_in[2];
    const float* pe   = (const float*)d_in[3];
    float* out = (float*)d_out;

    // Reordered so the big k_main occupies the launch slot ncu has been
    // capturing (previously always k_logits). Dependencies preserved:
    // transpose -> {bag, main}; bag -> logits.
    k_transpose<<<dim3(128, 4), dim3(32, 8)>>>(pe);
    k_bag<<<4096, 256>>>(x, out);
    k_logits<<<32, 256>>>(W, bias, out);
    k_main<<<dim3(32, 32), 128>>>(x, W, out);
}